// round 11
// baseline (speedup 1.0000x reference)
#include <cuda_runtime.h>
#include <math.h>
#include <stdint.h>

constexpr int kT    = 1024;
constexpr int kH    = 1024;
constexpr int kI    = 512;
constexpr int kE    = 16;
constexpr int kEAll = 18;     // + 2 shared-expert halves
constexpr int kTopK = 4;
constexpr int kNG   = 4;
constexpr int kGS   = kE / kNG;
constexpr int kTKG  = 2;
constexpr int kISH  = 1024;
constexpr float kScale = 2.5f;

// smem pipeline geometry (floats)
constexpr int kAStr   = 36;                   // 144B rows: 16B-aligned + conflict-free
constexpr int kBStr   = 136;                  // 544B rows: 16B-aligned + conflict-free
constexpr int kChunk  = 32;                   // K per chunk
constexpr int kAStage = 128 * kAStr;          // 4608 floats
constexpr int kBStage = kChunk * kBStr;       // 4352 floats
constexpr int kStage  = kAStage + kBStage;    // 8960 floats
constexpr int kStages = 3;
constexpr int kSmem   = kStages * kStage * 4; // 107520 B -> 2 CTAs/SM

// ---- device scratch ----
__device__ int   g_cnt[kEAll];
__device__ int   g_tok[kEAll * kT];
__device__ float g_coef[kEAll * kT];
__device__ int   g_tslot[kT * kTopK];
__device__ float g_h[(size_t)kEAll * kT * kI];
__device__ float g_o[(size_t)kEAll * kT * kH];
// tf32-pre-rounded copies
__device__ float g_rx[kT * kH];
__device__ float g_rwg[(size_t)kE * kH * kI];
__device__ float g_rwu[(size_t)kE * kH * kI];
__device__ float g_rwd[(size_t)kE * kI * kH];
__device__ float g_rswg[kH * kISH];
__device__ float g_rswu[kH * kISH];
__device__ float g_rswd[kISH * kH];

// ---------------------------------------------------------------------------
__device__ __forceinline__ float tf32r(float f) {
    uint32_t r; asm("cvt.rna.tf32.f32 %0, %1;" : "=r"(r) : "f"(f));
    return __uint_as_float(r);
}
__device__ __forceinline__ uint32_t smem_u32(const void* p) {
    uint32_t a;
    asm("{ .reg .u64 t; cvta.to.shared.u64 t, %1; cvt.u32.u64 %0, t; }"
        : "=r"(a) : "l"(p));
    return a;
}
__device__ __forceinline__ void cp16(uint32_t dst, const void* src) {
    asm volatile("cp.async.cg.shared.global [%0], [%1], 16;" :: "r"(dst), "l"(src));
}
__device__ __forceinline__ void cp_commit() {
    asm volatile("cp.async.commit_group;" ::: "memory");
}
__device__ __forceinline__ void cp_wait1() {
    asm volatile("cp.async.wait_group 1;" ::: "memory");
}
__device__ __forceinline__ void mma8(float* c,
                                     uint32_t a0, uint32_t a1, uint32_t a2, uint32_t a3,
                                     uint32_t b0, uint32_t b1) {
    asm volatile("mma.sync.aligned.m16n8k8.row.col.f32.tf32.tf32.f32 "
                 "{%0,%1,%2,%3},{%4,%5,%6,%7},{%8,%9},{%0,%1,%2,%3};\n"
                 : "+f"(c[0]), "+f"(c[1]), "+f"(c[2]), "+f"(c[3])
                 : "r"(a0), "r"(a1), "r"(a2), "r"(a3), "r"(b0), "r"(b1));
}

// ---------------------------------------------------------------------------
__global__ void init_kernel() {
    int i = blockIdx.x * blockDim.x + threadIdx.x;
    if (i < kE) g_cnt[i] = 0;
    if (i == kE || i == kE + 1) g_cnt[i] = kT;
    if (i < kT) {
        g_tok[kE * kT + i] = i;       g_coef[kE * kT + i] = 1.f;
        g_tok[(kE + 1) * kT + i] = i; g_coef[(kE + 1) * kT + i] = 1.f;
    }
}

// ---------------------------------------------------------------------------
// Pre-round all GEMM operands to tf32 (rna) once.
constexpr size_t kF4X   = (size_t)kT * kH / 4;
constexpr size_t kF4W   = (size_t)kE * kH * kI / 4;
constexpr size_t kF4S   = (size_t)kH * kISH / 4;

__global__ __launch_bounds__(256) void preround_kernel(
    const float4* __restrict__ x,  const float4* __restrict__ wg,
    const float4* __restrict__ wu, const float4* __restrict__ wd,
    const float4* __restrict__ swg, const float4* __restrict__ swu,
    const float4* __restrict__ swd)
{
    const size_t total = kF4X + 3 * kF4W + 3 * kF4S;
    for (size_t i = (size_t)blockIdx.x * blockDim.x + threadIdx.x;
         i < total; i += (size_t)gridDim.x * blockDim.x) {
        const float4* src; float4* dst; size_t j = i;
        if      (j < kF4X)               { src = x;   dst = (float4*)g_rx; }
        else if ((j -= kF4X) < kF4W)     { src = wg;  dst = (float4*)g_rwg; }
        else if ((j -= kF4W) < kF4W)     { src = wu;  dst = (float4*)g_rwu; }
        else if ((j -= kF4W) < kF4W)     { src = wd;  dst = (float4*)g_rwd; }
        else if ((j -= kF4W) < kF4S)     { src = swg; dst = (float4*)g_rswg; }
        else if ((j -= kF4S) < kF4S)     { src = swu; dst = (float4*)g_rswu; }
        else     { j -= kF4S;              src = swd; dst = (float4*)g_rswd; }
        float4 v = src[j];
        v.x = tf32r(v.x); v.y = tf32r(v.y); v.z = tf32r(v.z); v.w = tf32r(v.w);
        dst[j] = v;
    }
}

// ---------------------------------------------------------------------------
__global__ __launch_bounds__(512) void router_kernel(
    const float* __restrict__ x, const float* __restrict__ rw,
    const float* __restrict__ ebias)
{
    const int t = blockIdx.x;
    const int warp = threadIdx.x >> 5;
    const int lane = threadIdx.x & 31;
    __shared__ float logits[kE];

    const float* xr = x + (size_t)t * kH;
    float acc = 0.f;
    for (int h = lane; h < kH; h += 32)
        acc += xr[h] * rw[h * kE + warp];
    #pragma unroll
    for (int o = 16; o; o >>= 1) acc += __shfl_xor_sync(0xffffffffu, acc, o);
    if (lane == 0) logits[warp] = acc;
    __syncthreads();

    if (threadIdx.x == 0) {
        float scores[kE], sc[kE];
        #pragma unroll
        for (int e = 0; e < kE; e++) {
            float s = 1.f / (1.f + expf(-logits[e]));
            scores[e] = s;
            sc[e] = s + ebias[e];
        }
        float gs[kNG];
        #pragma unroll
        for (int g = 0; g < kNG; g++) {
            float m1 = -1e30f, m2 = -1e30f;
            #pragma unroll
            for (int j = 0; j < kGS; j++) {
                float v = sc[g * kGS + j];
                if (v > m1) { m2 = m1; m1 = v; }
                else if (v > m2) m2 = v;
            }
            gs[g] = m1 + m2;
        }
        bool gsel[kNG] = {false, false, false, false};
        for (int k = 0; k < kTKG; k++) {
            int bi = -1; float bv = -1e30f;
            for (int g = 0; g < kNG; g++)
                if (!gsel[g] && gs[g] > bv) { bv = gs[g]; bi = g; }
            gsel[bi] = true;
        }
        float masked[kE];
        #pragma unroll
        for (int e = 0; e < kE; e++)
            masked[e] = gsel[e / kGS] ? sc[e] : 0.f;
        int tidx[kTopK]; float w[kTopK]; float wsum = 0.f;
        bool used[kE];
        #pragma unroll
        for (int e = 0; e < kE; e++) used[e] = false;
        for (int k = 0; k < kTopK; k++) {
            int bi = -1; float bv = -1e30f;
            for (int e = 0; e < kE; e++)
                if (!used[e] && masked[e] > bv) { bv = masked[e]; bi = e; }
            used[bi] = true;
            tidx[k] = bi;
            w[k] = scores[bi];
            wsum += w[k];
        }
        float inv = kScale / (wsum + 1e-20f);
        for (int k = 0; k < kTopK; k++) {
            int e = tidx[k];
            int slot = atomicAdd(&g_cnt[e], 1);
            g_tok[e * kT + slot]  = t;
            g_coef[e * kT + slot] = w[k] * inv;
            g_tslot[t * kTopK + k] = e * kT + slot;
        }
    }
}

// ---------------------------------------------------------------------------
// Gate+up: 128-thread CTA, tile 128 rows x 64 I-cols (smem B: [64 g | 64 u]).
// 4 warps: mb=(w&1)*64, ng=(w>>1)*32 -> warp tile 64 x (32g+32u) = 64x64
// (LDS/mma = 1.0). cp.async 3-stage, ONE barrier per K32 chunk. 2 CTAs/SM.
__global__ __launch_bounds__(128, 2) void gateup_v6() {
    const int e = blockIdx.z;
    const int cnt = g_cnt[e];
    const int row0 = blockIdx.y * 128;
    if (row0 >= cnt) return;
    const int col0 = blockIdx.x * 64;

    extern __shared__ float sm[];
    const uint32_t smb = smem_u32(sm);

    const int tid = threadIdx.x;
    const int w = tid >> 5, l = tid & 31;
    const int qr = l >> 2, qc = l & 3;
    const int mb = (w & 1) * 64, ng = (w >> 1) * 32;

    const float *gb, *ub; int ldb;
    if (e < kE) {
        gb = g_rwg + (size_t)e * kH * kI;
        ub = g_rwu + (size_t)e * kH * kI;
        ldb = kI;
    } else {
        int off = (e - kE) * kI;
        gb = g_rswg + off; ub = g_rswu + off; ldb = kISH;
    }

    // A cp.async: 8 x cp16/thread; row = (tid>>3)+16p, kcols (tid&7)*4..+3
    uint32_t asof[8];                       // element offsets into g_rx
    #pragma unroll
    for (int p = 0; p < 8; p++) {
        int slot = row0 + (tid >> 3) + 16 * p;
        if (slot >= cnt) slot = cnt - 1;
        asof[p] = (uint32_t)g_tok[e * kT + slot] * kH + (tid & 7) * 4;
    }
    const uint32_t aoff0 = ((tid >> 3) * kAStr + (tid & 7) * 4) * 4;
    // B cp.async: 8 x cp16/thread; k = (tid>>5)+4p, smem col (tid&31)*4
    const float* bbase = ((tid & 31) < 16 ? gb : ub) + col0 + (tid & 15) * 4;
    const uint32_t bk0 = tid >> 5;
    const uint32_t boff0 = (kAStage + bk0 * kBStr + (tid & 31) * 4) * 4;

    float cg[4][4][4] = {}, cu[4][4][4] = {};

    constexpr int NCH = kH / kChunk;   // 32
    auto issue = [&](int ch, int s) {
        const uint32_t sb = smb + s * (kStage * 4);
        const int k0 = ch * kChunk;
        #pragma unroll
        for (int p = 0; p < 8; p++)
            cp16(sb + aoff0 + p * (16 * kAStr * 4), g_rx + asof[p] + k0);
        #pragma unroll
        for (int p = 0; p < 8; p++)
            cp16(sb + boff0 + p * (4 * kBStr * 4),
                 bbase + (size_t)(k0 + bk0 + 4 * p) * ldb - bk0 * (size_t)ldb
                       + bk0 * (size_t)ldb);  // = bbase + (k0+bk0+4p)*ldb
    };
    // simplified issue (the expression above folds): re-define cleanly
    auto issue2 = [&](int ch, int s) {
        const uint32_t sb = smb + s * (kStage * 4);
        const int k0 = ch * kChunk;
        #pragma unroll
        for (int p = 0; p < 8; p++)
            cp16(sb + aoff0 + p * (16 * kAStr * 4), g_rx + asof[p] + k0);
        #pragma unroll
        for (int p = 0; p < 8; p++)
            cp16(sb + boff0 + p * (4 * kBStr * 4),
                 bbase + (size_t)(k0 + (int)bk0 + 4 * p) * ldb);
    };
    (void)issue;
    issue2(0, 0); cp_commit();
    issue2(1, 1); cp_commit();

    for (int ch = 0; ch < NCH; ch++) {
        cp_wait1();
        __syncthreads();
        const float* As = sm + (ch % 3) * kStage;
        const float* Bs = As + kAStage;
        #pragma unroll
        for (int ks = 0; ks < kChunk; ks += 8) {
            uint32_t af[4][4];
            #pragma unroll
            for (int mt = 0; mt < 4; mt++) {
                int m = mb + mt * 16;
                af[mt][0] = __float_as_uint(As[(m + qr) * kAStr + ks + qc]);
                af[mt][1] = __float_as_uint(As[(m + qr + 8) * kAStr + ks + qc]);
                af[mt][2] = __float_as_uint(As[(m + qr) * kAStr + ks + qc + 4]);
                af[mt][3] = __float_as_uint(As[(m + qr + 8) * kAStr + ks + qc + 4]);
            }
            #pragma unroll
            for (int nt = 0; nt < 4; nt++) {
                int n = ng + nt * 8 + qr;
                uint32_t b0g = __float_as_uint(Bs[(ks + qc) * kBStr + n]);
                uint32_t b1g = __float_as_uint(Bs[(ks + qc + 4) * kBStr + n]);
                uint32_t b0u = __float_as_uint(Bs[(ks + qc) * kBStr + n + 64]);
                uint32_t b1u = __float_as_uint(Bs[(ks + qc + 4) * kBStr + n + 64]);
                #pragma unroll
                for (int mt = 0; mt < 4; mt++) {
                    mma8(cg[mt][nt], af[mt][0], af[mt][1], af[mt][2], af[mt][3], b0g, b1g);
                    mma8(cu[mt][nt], af[mt][0], af[mt][1], af[mt][2], af[mt][3], b0u, b1u);
                }
            }
        }
        if (ch + 2 < NCH) issue2(ch + 2, (ch + 2) % 3);
        cp_commit();
    }

    // Epilogue: h = coef * silu(g) * u (tf32 pre-rounded for the down GEMM)
    #pragma unroll
    for (int mt = 0; mt < 4; mt++) {
        #pragma unroll
        for (int pair = 0; pair < 2; pair++) {
            int r = row0 + mb + mt * 16 + qr + pair * 8;
            if (r < cnt) {
                float cf = g_coef[e * kT + r];
                float* hp = g_h + ((size_t)e * kT + r) * kI + col0 + ng;
                #pragma unroll
                for (int nt = 0; nt < 4; nt++) {
                    float g0 = cg[mt][nt][pair * 2 + 0];
                    float g1 = cg[mt][nt][pair * 2 + 1];
                    float u0 = cu[mt][nt][pair * 2 + 0];
                    float u1 = cu[mt][nt][pair * 2 + 1];
                    float h0 = cf * (g0 / (1.f + __expf(-g0))) * u0;
                    float h1 = cf * (g1 / (1.f + __expf(-g1))) * u1;
                    float2 st; st.x = tf32r(h0); st.y = tf32r(h1);
                    *(float2*)&hp[nt * 8 + 2 * qc] = st;
                }
            }
        }
    }
}

// ---------------------------------------------------------------------------
// Down-proj: 128-thread CTA, tile 128 rows x 128 H-cols.
// 4 warps: mb=(w&1)*64, nw=(w>>1)*64 -> warp tile 64x64. 2 CTAs/SM.
__global__ __launch_bounds__(128, 2) void down_v6() {
    const int e = blockIdx.z;
    const int cnt = g_cnt[e];
    const int row0 = blockIdx.y * 128;
    if (row0 >= cnt) return;
    const int col0 = blockIdx.x * 128;

    extern __shared__ float sm[];
    const uint32_t smb = smem_u32(sm);

    const int tid = threadIdx.x;
    const int w = tid >> 5, l = tid & 31;
    const int qr = l >> 2, qc = l & 3;
    const int mb = (w & 1) * 64, nw = (w >> 1) * 64;

    const float* bw = (e < kE) ? (g_rwd + (size_t)e * kI * kH)
                               : (g_rswd + (size_t)(e - kE) * kI * kH);

    const float* abase = g_h + ((size_t)e * kT + row0 + (tid >> 3)) * kI + (tid & 7) * 4;
    const uint32_t aoff0 = ((tid >> 3) * kAStr + (tid & 7) * 4) * 4;
    const float* bbase = bw + col0 + (tid & 31) * 4;
    const uint32_t bk0 = tid >> 5;
    const uint32_t boff0 = (kAStage + bk0 * kBStr + (tid & 31) * 4) * 4;

    float c[4][8][4] = {};

    constexpr int NCH = kI / kChunk;   // 16
    auto issue = [&](int ch, int s) {
        const uint32_t sb = smb + s * (kStage * 4);
        const int k0 = ch * kChunk;
        #pragma unroll
        for (int p = 0; p < 8; p++)
            cp16(sb + aoff0 + p * (16 * kAStr * 4),
                 abase + (size_t)(16 * p) * kI + k0);
        #pragma unroll
        for (int p = 0; p < 8; p++)
            cp16(sb + boff0 + p * (4 * kBStr * 4),
                 bbase + (size_t)(k0 + (int)bk0 + 4 * p) * kH);
    };
    issue(0, 0); cp_commit();
    issue(1, 1); cp_commit();

    for (int ch = 0; ch < NCH; ch++) {
        cp_wait1();
        __syncthreads();
        const float* As = sm + (ch % 3) * kStage;
        const float* Bs = As + kAStage;
        #pragma unroll
        for (int ks = 0; ks < kChunk; ks += 8) {
            uint32_t af[4][4];
            #pragma unroll
            for (int mt = 0; mt < 4; mt++) {
                int m = mb + mt * 16;
                af[mt][0] = __float_as_uint(As[(m + qr) * kAStr + ks + qc]);
                af[mt][1] = __float_as_uint(As[(m + qr + 8) * kAStr + ks + qc]);
                af[mt][2] = __float_as_uint(As[(m + qr) * kAStr + ks + qc + 4]);
                af[mt][3] = __float_as_uint(As[(m + qr + 8) * kAStr + ks + qc + 4]);
            }
            #pragma unroll
            for (int nt = 0; nt < 8; nt++) {
                int n = nw + nt * 8 + qr;
                uint32_t b0 = __float_as_uint(Bs[(ks + qc) * kBStr + n]);
                uint32_t b1 = __float_as_uint(Bs[(ks + qc + 4) * kBStr + n]);
                #pragma unroll
                for (int mt = 0; mt < 4; mt++)
                    mma8(c[mt][nt], af[mt][0], af[mt][1], af[mt][2], af[mt][3], b0, b1);
            }
        }
        if (ch + 2 < NCH) issue(ch + 2, (ch + 2) % 3);
        cp_commit();
    }

    #pragma unroll
    for (int mt = 0; mt < 4; mt++) {
        #pragma unroll
        for (int pair = 0; pair < 2; pair++) {
            int r = row0 + mb + mt * 16 + qr + pair * 8;
            if (r < cnt) {
                float* op = g_o + ((size_t)e * kT + r) * kH + col0 + nw;
                #pragma unroll
                for (int nt = 0; nt < 8; nt++) {
                    float2 st;
                    st.x = c[mt][nt][pair * 2 + 0];
                    st.y = c[mt][nt][pair * 2 + 1];
                    *(float2*)&op[nt * 8 + 2 * qc] = st;
                }
            }
        }
    }
}

// ---------------------------------------------------------------------------
__global__ __launch_bounds__(256) void combine_kernel(float* __restrict__ out) {
    const int t = blockIdx.x;
    const int c = threadIdx.x * 4;
    int s0 = g_tslot[t * kTopK + 0], s1 = g_tslot[t * kTopK + 1];
    int s2 = g_tslot[t * kTopK + 2], s3 = g_tslot[t * kTopK + 3];
    float4 a = *(const float4*)&g_o[(size_t)s0 * kH + c];
    float4 b = *(const float4*)&g_o[(size_t)s1 * kH + c];
    float4 d = *(const float4*)&g_o[(size_t)s2 * kH + c];
    float4 e4 = *(const float4*)&g_o[(size_t)s3 * kH + c];
    float4 f = *(const float4*)&g_o[((size_t)kE * kT + t) * kH + c];
    float4 g = *(const float4*)&g_o[((size_t)(kE + 1) * kT + t) * kH + c];
    float4 r;
    r.x = a.x + b.x + d.x + e4.x + f.x + g.x;
    r.y = a.y + b.y + d.y + e4.y + f.y + g.y;
    r.z = a.z + b.z + d.z + e4.z + f.z + g.z;
    r.w = a.w + b.w + d.w + e4.w + f.w + g.w;
    *(float4*)&out[(size_t)t * kH + c] = r;
}

// ---------------------------------------------------------------------------
extern "C" void kernel_launch(void* const* d_in, const int* in_sizes, int n_in,
                              void* d_out, int out_size) {
    const float* x   = (const float*)d_in[0];
    const float* rw  = (const float*)d_in[1];
    const float* eb  = (const float*)d_in[2];
    const float* wg  = (const float*)d_in[3];
    const float* wu  = (const float*)d_in[4];
    const float* wd  = (const float*)d_in[5];
    const float* swg = (const float*)d_in[6];
    const float* swu = (const float*)d_in[7];
    const float* swd = (const float*)d_in[8];
    float* out = (float*)d_out;

    cudaFuncSetAttribute(gateup_v6, cudaFuncAttributeMaxDynamicSharedMemorySize, kSmem);
    cudaFuncSetAttribute(down_v6,   cudaFuncAttributeMaxDynamicSharedMemorySize, kSmem);

    init_kernel<<<4, 256>>>();
    router_kernel<<<kT, 512>>>(x, rw, eb);
    preround_kernel<<<1024, 256>>>((const float4*)x, (const float4*)wg,
                                   (const float4*)wu, (const float4*)wd,
                                   (const float4*)swg, (const float4*)swu,
                                   (const float4*)swd);
    gateup_v6<<<dim3(8, 8, kEAll), 128, kSmem>>>();
    down_v6<<<dim3(8, 8, kEAll), 128, kSmem>>>();
    combine_kernel<<<kT, 256>>>(out);
}

// round 12
// speedup vs baseline: 1.9803x; 1.9803x over previous
#include <cuda_runtime.h>
#include <cuda_fp16.h>
#include <math.h>
#include <stdint.h>

constexpr int kT    = 1024;
constexpr int kH    = 1024;
constexpr int kI    = 512;
constexpr int kE    = 16;
constexpr int kEAll = 18;     // + 2 shared-expert halves
constexpr int kTopK = 4;
constexpr int kNG   = 4;
constexpr int kGS   = kE / kNG;
constexpr int kTKG  = 2;
constexpr int kISH  = 1024;
constexpr float kScale = 2.5f;

// smem pipeline geometry (halves)
constexpr int kChunk  = 64;                    // K per chunk
constexpr int kAStrH  = 72;                    // 144B rows: 16B-aligned, LDSM conflict-free
constexpr int kBStrH  = 136;                   // 272B rows: 16B-aligned, LDSM conflict-free
constexpr int kAStageH = 128 * kAStrH;         // 9216 halves
constexpr int kBStageH = kChunk * kBStrH;      // 8704 halves
constexpr int kStageB  = (kAStageH + kBStageH) * 2;   // 35840 bytes
constexpr int kStages  = 3;
constexpr int kSmem    = kStages * kStageB;    // 107520 B -> 2 CTAs/SM

// ---- device scratch ----
__device__ int    g_cnt[kEAll];
__device__ int    g_tok[kEAll * kT];
__device__ float  g_coef[kEAll * kT];
__device__ int    g_tslot[kT * kTopK];
__device__ __half g_h[(size_t)kEAll * kT * kI];
__device__ float  g_o[(size_t)kEAll * kT * kH];
// fp16-pre-rounded copies
__device__ __half g_rx[kT * kH];
__device__ __half g_rwg[(size_t)kE * kH * kI];
__device__ __half g_rwu[(size_t)kE * kH * kI];
__device__ __half g_rwd[(size_t)kE * kI * kH];
__device__ __half g_rswg[kH * kISH];
__device__ __half g_rswu[kH * kISH];
__device__ __half g_rswd[kISH * kH];

// ---------------------------------------------------------------------------
__device__ __forceinline__ uint32_t smem_u32(const void* p) {
    uint32_t a;
    asm("{ .reg .u64 t; cvta.to.shared.u64 t, %1; cvt.u32.u64 %0, t; }"
        : "=r"(a) : "l"(p));
    return a;
}
__device__ __forceinline__ void cp16(uint32_t dst, const void* src) {
    asm volatile("cp.async.cg.shared.global [%0], [%1], 16;" :: "r"(dst), "l"(src));
}
__device__ __forceinline__ void cp_commit() {
    asm volatile("cp.async.commit_group;" ::: "memory");
}
__device__ __forceinline__ void cp_wait1() {
    asm volatile("cp.async.wait_group 1;" ::: "memory");
}
__device__ __forceinline__ void ldsm4(uint32_t* r, uint32_t a) {
    asm volatile("ldmatrix.sync.aligned.m8n8.x4.shared.b16 {%0,%1,%2,%3}, [%4];"
                 : "=r"(r[0]), "=r"(r[1]), "=r"(r[2]), "=r"(r[3]) : "r"(a));
}
__device__ __forceinline__ void ldsm4t(uint32_t* r, uint32_t a) {
    asm volatile("ldmatrix.sync.aligned.m8n8.x4.trans.shared.b16 {%0,%1,%2,%3}, [%4];"
                 : "=r"(r[0]), "=r"(r[1]), "=r"(r[2]), "=r"(r[3]) : "r"(a));
}
__device__ __forceinline__ void mma16(float* c, const uint32_t* a,
                                      uint32_t b0, uint32_t b1) {
    asm volatile("mma.sync.aligned.m16n8k16.row.col.f32.f16.f16.f32 "
                 "{%0,%1,%2,%3},{%4,%5,%6,%7},{%8,%9},{%0,%1,%2,%3};\n"
                 : "+f"(c[0]), "+f"(c[1]), "+f"(c[2]), "+f"(c[3])
                 : "r"(a[0]), "r"(a[1]), "r"(a[2]), "r"(a[3]), "r"(b0), "r"(b1));
}

// ---------------------------------------------------------------------------
__global__ void init_kernel() {
    int i = blockIdx.x * blockDim.x + threadIdx.x;
    if (i < kE) g_cnt[i] = 0;
    if (i == kE || i == kE + 1) g_cnt[i] = kT;
    if (i < kT) {
        g_tok[kE * kT + i] = i;       g_coef[kE * kT + i] = 1.f;
        g_tok[(kE + 1) * kT + i] = i; g_coef[(kE + 1) * kT + i] = 1.f;
    }
}

// ---------------------------------------------------------------------------
// Pre-round all GEMM operands to fp16 (rn) once.
constexpr size_t kF4X = (size_t)kT * kH / 4;
constexpr size_t kF4W = (size_t)kE * kH * kI / 4;
constexpr size_t kF4S = (size_t)kH * kISH / 4;

__global__ __launch_bounds__(256) void preround_kernel(
    const float4* __restrict__ x,  const float4* __restrict__ wg,
    const float4* __restrict__ wu, const float4* __restrict__ wd,
    const float4* __restrict__ swg, const float4* __restrict__ swu,
    const float4* __restrict__ swd)
{
    const size_t total = kF4X + 3 * kF4W + 3 * kF4S;
    for (size_t i = (size_t)blockIdx.x * blockDim.x + threadIdx.x;
         i < total; i += (size_t)gridDim.x * blockDim.x) {
        const float4* src; __half* dst; size_t j = i;
        if      (j < kF4X)           { src = x;   dst = g_rx; }
        else if ((j -= kF4X) < kF4W) { src = wg;  dst = g_rwg; }
        else if ((j -= kF4W) < kF4W) { src = wu;  dst = g_rwu; }
        else if ((j -= kF4W) < kF4W) { src = wd;  dst = g_rwd; }
        else if ((j -= kF4W) < kF4S) { src = swg; dst = g_rswg; }
        else if ((j -= kF4S) < kF4S) { src = swu; dst = g_rswu; }
        else { j -= kF4S;              src = swd; dst = g_rswd; }
        float4 v = src[j];
        __half2 h0 = __floats2half2_rn(v.x, v.y);
        __half2 h1 = __floats2half2_rn(v.z, v.w);
        __half2* d2 = (__half2*)(dst + j * 4);
        d2[0] = h0; d2[1] = h1;
    }
}

// ---------------------------------------------------------------------------
__global__ __launch_bounds__(512) void router_kernel(
    const float* __restrict__ x, const float* __restrict__ rw,
    const float* __restrict__ ebias)
{
    const int t = blockIdx.x;
    const int warp = threadIdx.x >> 5;
    const int lane = threadIdx.x & 31;
    __shared__ float logits[kE];

    const float* xr = x + (size_t)t * kH;
    float acc = 0.f;
    for (int h = lane; h < kH; h += 32)
        acc += xr[h] * rw[h * kE + warp];
    #pragma unroll
    for (int o = 16; o; o >>= 1) acc += __shfl_xor_sync(0xffffffffu, acc, o);
    if (lane == 0) logits[warp] = acc;
    __syncthreads();

    if (threadIdx.x == 0) {
        float scores[kE], sc[kE];
        #pragma unroll
        for (int e = 0; e < kE; e++) {
            float s = 1.f / (1.f + expf(-logits[e]));
            scores[e] = s;
            sc[e] = s + ebias[e];
        }
        float gs[kNG];
        #pragma unroll
        for (int g = 0; g < kNG; g++) {
            float m1 = -1e30f, m2 = -1e30f;
            #pragma unroll
            for (int j = 0; j < kGS; j++) {
                float v = sc[g * kGS + j];
                if (v > m1) { m2 = m1; m1 = v; }
                else if (v > m2) m2 = v;
            }
            gs[g] = m1 + m2;
        }
        bool gsel[kNG] = {false, false, false, false};
        for (int k = 0; k < kTKG; k++) {
            int bi = -1; float bv = -1e30f;
            for (int g = 0; g < kNG; g++)
                if (!gsel[g] && gs[g] > bv) { bv = gs[g]; bi = g; }
            gsel[bi] = true;
        }
        float masked[kE];
        #pragma unroll
        for (int e = 0; e < kE; e++)
            masked[e] = gsel[e / kGS] ? sc[e] : 0.f;
        int tidx[kTopK]; float w[kTopK]; float wsum = 0.f;
        bool used[kE];
        #pragma unroll
        for (int e = 0; e < kE; e++) used[e] = false;
        for (int k = 0; k < kTopK; k++) {
            int bi = -1; float bv = -1e30f;
            for (int e = 0; e < kE; e++)
                if (!used[e] && masked[e] > bv) { bv = masked[e]; bi = e; }
            used[bi] = true;
            tidx[k] = bi;
            w[k] = scores[bi];
            wsum += w[k];
        }
        float inv = kScale / (wsum + 1e-20f);
        for (int k = 0; k < kTopK; k++) {
            int e = tidx[k];
            int slot = atomicAdd(&g_cnt[e], 1);
            g_tok[e * kT + slot]  = t;
            g_coef[e * kT + slot] = w[k] * inv;
            g_tslot[t * kTopK + k] = e * kT + slot;
        }
    }
}

// ---------------------------------------------------------------------------
// Gate+up: 256-thread CTA, tile 128 rows x 64 I-cols; smem B = [64 g | 64 u].
// 8 warps: mb=(w&3)*32, nb=(w>>2)*32. fp16 m16n8k16 + ldmatrix.
// cp.async 3-stage, K64 chunks, ONE barrier per chunk. 2 CTAs/SM.
__global__ __launch_bounds__(256, 2) void gateup_v7() {
    const int e = blockIdx.z;
    const int cnt = g_cnt[e];
    const int row0 = blockIdx.y * 128;
    if (row0 >= cnt) return;
    const int col0 = blockIdx.x * 64;

    extern __shared__ __half sm[];
    const uint32_t smb = smem_u32(sm);

    const int tid = threadIdx.x;
    const int w = tid >> 5, l = tid & 31;
    const int qr = l >> 2, qc = l & 3;
    const int mb = (w & 3) * 32, nb = (w >> 2) * 32;

    const __half *gb, *ub; int ldb;
    if (e < kE) {
        gb = g_rwg + (size_t)e * kH * kI;
        ub = g_rwu + (size_t)e * kH * kI;
        ldb = kI;
    } else {
        int off = (e - kE) * kI;
        gb = g_rswg + off; ub = g_rswu + off; ldb = kISH;
    }

    // A cp.async: row = tid>>1 (one token/thread), 4 x 8-half groups
    int aslot = row0 + (tid >> 1); if (aslot >= cnt) aslot = cnt - 1;
    const __half* abase = g_rx + (size_t)g_tok[e * kT + aslot] * kH + (tid & 1) * 32;
    const uint32_t aoff0 = ((tid >> 1) * kAStrH + (tid & 1) * 32) * 2;
    // B cp.async: k = tid>>4 (+16p), ng = tid&15 -> n = ng*8 (gate<64, up>=64)
    const int ng = tid & 15;
    const __half* bbase = ((ng < 8) ? (gb + col0 + ng * 8)
                                    : (ub + col0 + (ng - 8) * 8))
                          + (size_t)(tid >> 4) * ldb;
    const uint32_t boff0 = (kAStageH + (tid >> 4) * kBStrH + ng * 8) * 2;

    // ldmatrix lane-invariant offsets (halves)
    const uint32_t aF = (mb + ((l >> 3) & 1) * 8 + (l & 7)) * kAStrH + (l >> 4) * 8;
    const uint32_t bF = (((l >> 3) & 1) * 8 + (l & 7)) * kBStrH + (l >> 4) * 8;

    float cg[2][4][4] = {}, cu[2][4][4] = {};

    constexpr int NCH = kH / kChunk;   // 16
    auto issue = [&](int ch, int s) {
        const uint32_t sb = smb + s * kStageB;
        const int k0 = ch * kChunk;
        #pragma unroll
        for (int p = 0; p < 4; p++)
            cp16(sb + aoff0 + p * 16, abase + k0 + p * 8);
        #pragma unroll
        for (int p = 0; p < 4; p++)
            cp16(sb + boff0 + p * (16 * kBStrH * 2),
                 bbase + (size_t)(k0 + 16 * p) * ldb);
    };
    issue(0, 0); cp_commit();
    issue(1, 1); cp_commit();

    for (int ch = 0; ch < NCH; ch++) {
        cp_wait1();
        __syncthreads();
        const uint32_t sA = smb + (ch % 3) * kStageB;
        const uint32_t sB = sA + kAStageH * 2;
        #pragma unroll
        for (int ks = 0; ks < kChunk; ks += 16) {
            uint32_t a[2][4];
            #pragma unroll
            for (int mt = 0; mt < 2; mt++)
                ldsm4(a[mt], sA + (aF + mt * 16 * kAStrH + ks) * 2);
            #pragma unroll
            for (int blk = 0; blk < 2; blk++) {
                uint32_t bg[4], bu[4];
                uint32_t bad = sB + (bF + ks * kBStrH + nb + blk * 16) * 2;
                ldsm4t(bg, bad);
                ldsm4t(bu, bad + 64 * 2);
                #pragma unroll
                for (int sub = 0; sub < 2; sub++) {
                    int nt = blk * 2 + sub;
                    #pragma unroll
                    for (int mt = 0; mt < 2; mt++) {
                        mma16(cg[mt][nt], a[mt], bg[sub * 2], bg[sub * 2 + 1]);
                        mma16(cu[mt][nt], a[mt], bu[sub * 2], bu[sub * 2 + 1]);
                    }
                }
            }
        }
        if (ch + 2 < NCH) issue(ch + 2, (ch + 2) % 3);
        cp_commit();
    }

    // Epilogue: h = coef * silu(g) * u  (fp16 for the down GEMM)
    #pragma unroll
    for (int mt = 0; mt < 2; mt++) {
        #pragma unroll
        for (int pair = 0; pair < 2; pair++) {
            int r = row0 + mb + mt * 16 + qr + pair * 8;
            if (r < cnt) {
                float cf = g_coef[e * kT + r];
                __half* hp = g_h + ((size_t)e * kT + r) * kI + col0 + nb;
                #pragma unroll
                for (int nt = 0; nt < 4; nt++) {
                    float g0 = cg[mt][nt][pair * 2 + 0];
                    float g1 = cg[mt][nt][pair * 2 + 1];
                    float u0 = cu[mt][nt][pair * 2 + 0];
                    float u1 = cu[mt][nt][pair * 2 + 1];
                    float h0 = cf * (g0 / (1.f + __expf(-g0))) * u0;
                    float h1 = cf * (g1 / (1.f + __expf(-g1))) * u1;
                    *(__half2*)&hp[nt * 8 + 2 * qc] = __floats2half2_rn(h0, h1);
                }
            }
        }
    }
}

// ---------------------------------------------------------------------------
// Down-proj: 256-thread CTA, tile 128 rows x 128 H-cols.
// 8 warps: mb=(w&3)*32, nw=(w>>2)*64. fp16 m16n8k16 + ldmatrix. 2 CTAs/SM.
__global__ __launch_bounds__(256, 2) void down_v7() {
    const int e = blockIdx.z;
    const int cnt = g_cnt[e];
    const int row0 = blockIdx.y * 128;
    if (row0 >= cnt) return;
    const int col0 = blockIdx.x * 128;

    extern __shared__ __half sm[];
    const uint32_t smb = smem_u32(sm);

    const int tid = threadIdx.x;
    const int w = tid >> 5, l = tid & 31;
    const int qr = l >> 2, qc = l & 3;
    const int mb = (w & 3) * 32, nw = (w >> 2) * 64;

    const __half* bw = (e < kE) ? (g_rwd + (size_t)e * kI * kH)
                                : (g_rswd + (size_t)(e - kE) * kI * kH);

    const __half* abase = g_h + ((size_t)e * kT + row0 + (tid >> 1)) * kI + (tid & 1) * 32;
    const uint32_t aoff0 = ((tid >> 1) * kAStrH + (tid & 1) * 32) * 2;
    const int ng = tid & 15;
    const __half* bbase = bw + col0 + ng * 8 + (size_t)(tid >> 4) * kH;
    const uint32_t boff0 = (kAStageH + (tid >> 4) * kBStrH + ng * 8) * 2;

    const uint32_t aF = (mb + ((l >> 3) & 1) * 8 + (l & 7)) * kAStrH + (l >> 4) * 8;
    const uint32_t bF = (((l >> 3) & 1) * 8 + (l & 7)) * kBStrH + (l >> 4) * 8;

    float c[2][8][4] = {};

    constexpr int NCH = kI / kChunk;   // 8
    auto issue = [&](int ch, int s) {
        const uint32_t sb = smb + s * kStageB;
        const int k0 = ch * kChunk;
        #pragma unroll
        for (int p = 0; p < 4; p++)
            cp16(sb + aoff0 + p * 16, abase + k0 + p * 8);
        #pragma unroll
        for (int p = 0; p < 4; p++)
            cp16(sb + boff0 + p * (16 * kBStrH * 2),
                 bbase + (size_t)(k0 + 16 * p) * kH);
    };
    issue(0, 0); cp_commit();
    issue(1, 1); cp_commit();

    for (int ch = 0; ch < NCH; ch++) {
        cp_wait1();
        __syncthreads();
        const uint32_t sA = smb + (ch % 3) * kStageB;
        const uint32_t sB = sA + kAStageH * 2;
        #pragma unroll
        for (int ks = 0; ks < kChunk; ks += 16) {
            uint32_t a[2][4];
            #pragma unroll
            for (int mt = 0; mt < 2; mt++)
                ldsm4(a[mt], sA + (aF + mt * 16 * kAStrH + ks) * 2);
            #pragma unroll
            for (int blk = 0; blk < 4; blk++) {
                uint32_t b[4];
                ldsm4t(b, sB + (bF + ks * kBStrH + nw + blk * 16) * 2);
                #pragma unroll
                for (int sub = 0; sub < 2; sub++) {
                    int nt = blk * 2 + sub;
                    #pragma unroll
                    for (int mt = 0; mt < 2; mt++)
                        mma16(c[mt][nt], a[mt], b[sub * 2], b[sub * 2 + 1]);
                }
            }
        }
        if (ch + 2 < NCH) issue(ch + 2, (ch + 2) % 3);
        cp_commit();
    }

    #pragma unroll
    for (int mt = 0; mt < 2; mt++) {
        #pragma unroll
        for (int pair = 0; pair < 2; pair++) {
            int r = row0 + mb + mt * 16 + qr + pair * 8;
            if (r < cnt) {
                float* op = g_o + ((size_t)e * kT + r) * kH + col0 + nw;
                #pragma unroll
                for (int nt = 0; nt < 8; nt++) {
                    float2 st;
                    st.x = c[mt][nt][pair * 2 + 0];
                    st.y = c[mt][nt][pair * 2 + 1];
                    *(float2*)&op[nt * 8 + 2 * qc] = st;
                }
            }
        }
    }
}

// ---------------------------------------------------------------------------
__global__ __launch_bounds__(256) void combine_kernel(float* __restrict__ out) {
    const int t = blockIdx.x;
    const int c = threadIdx.x * 4;
    int s0 = g_tslot[t * kTopK + 0], s1 = g_tslot[t * kTopK + 1];
    int s2 = g_tslot[t * kTopK + 2], s3 = g_tslot[t * kTopK + 3];
    float4 a = *(const float4*)&g_o[(size_t)s0 * kH + c];
    float4 b = *(const float4*)&g_o[(size_t)s1 * kH + c];
    float4 d = *(const float4*)&g_o[(size_t)s2 * kH + c];
    float4 e4 = *(const float4*)&g_o[(size_t)s3 * kH + c];
    float4 f = *(const float4*)&g_o[((size_t)kE * kT + t) * kH + c];
    float4 g = *(const float4*)&g_o[((size_t)(kE + 1) * kT + t) * kH + c];
    float4 r;
    r.x = a.x + b.x + d.x + e4.x + f.x + g.x;
    r.y = a.y + b.y + d.y + e4.y + f.y + g.y;
    r.z = a.z + b.z + d.z + e4.z + f.z + g.z;
    r.w = a.w + b.w + d.w + e4.w + f.w + g.w;
    *(float4*)&out[(size_t)t * kH + c] = r;
}

// ---------------------------------------------------------------------------
extern "C" void kernel_launch(void* const* d_in, const int* in_sizes, int n_in,
                              void* d_out, int out_size) {
    const float* x   = (const float*)d_in[0];
    const float* rw  = (const float*)d_in[1];
    const float* eb  = (const float*)d_in[2];
    const float* wg  = (const float*)d_in[3];
    const float* wu  = (const float*)d_in[4];
    const float* wd  = (const float*)d_in[5];
    const float* swg = (const float*)d_in[6];
    const float* swu = (const float*)d_in[7];
    const float* swd = (const float*)d_in[8];
    float* out = (float*)d_out;

    cudaFuncSetAttribute(gateup_v7, cudaFuncAttributeMaxDynamicSharedMemorySize, kSmem);
    cudaFuncSetAttribute(down_v7,   cudaFuncAttributeMaxDynamicSharedMemorySize, kSmem);

    init_kernel<<<4, 256>>>();
    router_kernel<<<kT, 512>>>(x, rw, eb);
    preround_kernel<<<1024, 256>>>((const float4*)x, (const float4*)wg,
                                   (const float4*)wu, (const float4*)wd,
                                   (const float4*)swg, (const float4*)swu,
                                   (const float4*)swd);
    gateup_v7<<<dim3(8, 8, kEAll), 256, kSmem>>>();
    down_v7<<<dim3(8, 8, kEAll), 256, kSmem>>>();
    combine_kernel<<<kT, 256>>>(out);
}